// round 12
// baseline (speedup 1.0000x reference)
#include <cuda_runtime.h>
#include <cstdint>

#define NB 16384
#define NI 512
#define NO 2048

#define BM 128
#define BN 64
#define BK 64
#define KCH (NI / BK)     // 8
#define THREADS 256
#define NCTA 296                            // 2 CTAs x 148 SMs, persistent
#define NTILES ((NB / BM) * (NO / BN))      // 128 * 32 = 4096
#define USTRIDE 36                          // u32 per row: 32 data + 4 pad
#define APLANE_U (128 * USTRIDE)            // 4608
#define BPLANE_U (64 * USTRIDE)             // 2304
#define STAGE_U (2 * APLANE_U + 2 * BPLANE_U)  // 13824 u32 = 55296 B
#define SMEM_BYTES (2 * STAGE_U * 4)        // 110592 B

// ---------------------------------------------------------------------------
// scratch (device globals — no allocations allowed)
// ---------------------------------------------------------------------------
__device__ uint16_t g_xh[(size_t)NB * NI];   // fp16 hi plane of x/||x||
__device__ uint16_t g_xl[(size_t)NB * NI];   // fp16 lo plane
__device__ uint16_t g_wh[(size_t)NO * NI];
__device__ uint16_t g_wl[(size_t)NO * NI];
__device__ float g_cos[(size_t)NB * NO];

// ---------------------------------------------------------------------------
// helpers
// ---------------------------------------------------------------------------
__device__ __forceinline__ uint32_t smem_u32(const void* p) {
    uint32_t a;
    asm("{ .reg .u64 t; cvta.to.shared.u64 t, %1; cvt.u32.u64 %0, t; }" : "=r"(a) : "l"(p));
    return a;
}
__device__ __forceinline__ void cp_async16(uint32_t dst, const void* src) {
    asm volatile("cp.async.cg.shared.global [%0], [%1], 16;" :: "r"(dst), "l"(src));
}
__device__ __forceinline__ void cp_commit() {
    asm volatile("cp.async.commit_group;" ::: "memory");
}
template <int N>
__device__ __forceinline__ void cp_wait() {
    asm volatile("cp.async.wait_group %0;" :: "n"(N) : "memory");
}
// fp16 2-split: x = h + l (exact to ~2^-24 relative)
__device__ __forceinline__ void f16_split(float x, uint16_t& h, uint16_t& l) {
    asm("cvt.rn.f16.f32 %0, %1;" : "=h"(h) : "f"(x));
    float hf;
    asm("cvt.f32.f16 %0, %1;" : "=f"(hf) : "h"(h));
    const float r = x - hf;
    asm("cvt.rn.f16.f32 %0, %1;" : "=h"(l) : "f"(r));
}
// d += a*b   (m16n8k16 fp16 -> fp32)
__device__ __forceinline__ void mma_acc(float* d, const uint32_t* a, const uint32_t* b) {
    asm volatile(
        "mma.sync.aligned.m16n8k16.row.col.f32.f16.f16.f32 "
        "{%0,%1,%2,%3}, {%4,%5,%6,%7}, {%8,%9}, {%0,%1,%2,%3};"
        : "+f"(d[0]), "+f"(d[1]), "+f"(d[2]), "+f"(d[3])
        : "r"(a[0]), "r"(a[1]), "r"(a[2]), "r"(a[3]), "r"(b[0]), "r"(b[1]));
}
// d = a*b (fresh accumulation chain)
__device__ __forceinline__ void mma_zero(float* d, const uint32_t* a, const uint32_t* b) {
    asm volatile(
        "mma.sync.aligned.m16n8k16.row.col.f32.f16.f16.f32 "
        "{%0,%1,%2,%3}, {%4,%5,%6,%7}, {%8,%9}, {%10,%11,%12,%13};"
        : "=f"(d[0]), "=f"(d[1]), "=f"(d[2]), "=f"(d[3])
        : "r"(a[0]), "r"(a[1]), "r"(a[2]), "r"(a[3]), "r"(b[0]), "r"(b[1]),
          "f"(0.0f), "f"(0.0f), "f"(0.0f), "f"(0.0f));
}

// ---------------------------------------------------------------------------
// prep: normalize each row (/(max(||row||, eps))) and write fp16 hi/lo planes.
// ---------------------------------------------------------------------------
__global__ __launch_bounds__(128) void prep_kernel(
    const float* __restrict__ src, uint16_t* __restrict__ Hi,
    uint16_t* __restrict__ Lo) {
    const int row = blockIdx.x;
    const int tid = threadIdx.x;
    const float4 v = reinterpret_cast<const float4*>(src + (size_t)row * NI)[tid];
    float s = v.x * v.x + v.y * v.y + v.z * v.z + v.w * v.w;
#pragma unroll
    for (int o = 16; o; o >>= 1) s += __shfl_xor_sync(0xffffffffu, s, o);
    __shared__ float ws[4];
    __shared__ float sh_inv;
    if ((tid & 31) == 0) ws[tid >> 5] = s;
    __syncthreads();
    if (tid == 0) {
        const float t = ws[0] + ws[1] + ws[2] + ws[3];
        sh_inv = 1.0f / fmaxf(sqrtf(t), 1e-8f);
    }
    __syncthreads();
    const float inv = sh_inv;

    uint16_t h0, l0, h1, l1, h2, l2, h3, l3;
    f16_split(v.x * inv, h0, l0);
    f16_split(v.y * inv, h1, l1);
    f16_split(v.z * inv, h2, l2);
    f16_split(v.w * inv, h3, l3);
    uint2 ph, pl;
    ph.x = (uint32_t)h0 | ((uint32_t)h1 << 16);
    ph.y = (uint32_t)h2 | ((uint32_t)h3 << 16);
    pl.x = (uint32_t)l0 | ((uint32_t)l1 << 16);
    pl.y = (uint32_t)l2 | ((uint32_t)l3 << 16);
    reinterpret_cast<uint2*>(Hi + (size_t)row * NI)[tid] = ph;
    reinterpret_cast<uint2*>(Lo + (size_t)row * NI)[tid] = pl;
}

// ---------------------------------------------------------------------------
// Persistent 3xFP16 warp-mma GEMM on pre-normalized pre-split planes:
//   cos[b,o] = dot(xn[b,:], wn[o,:])  via hh + hl + lh
// 296 persistent CTAs; each walks tiles t = bid, bid+296, ... with a FLAT
// chunk loop (chunk = tile*8 + kc) so the 2-stage cp.async pipeline runs
// continuously across tile boundaries. Inner math identical to R7/R9
// (bit-identical results): 6-MMA temp chains, RN flush to fp32 master.
// ---------------------------------------------------------------------------
__global__ __launch_bounds__(THREADS, 2)
void gemm_tc() {
    extern __shared__ uint32_t smem[];   // [2 stages][Ah|Al|Bh|Bl]

    const int tid = threadIdx.x;
    const int wid = tid >> 5;
    const int lane = tid & 31;
    const int bid = blockIdx.x;
    const int warpM = wid & 1;   // 2
    const int warpN = wid >> 1;  // 4
    const int g = lane >> 2;     // 0..7
    const int t4 = lane & 3;     // 0..3

    const int ntilesLocal = (NTILES - bid + NCTA - 1) / NCTA;   // 13 or 14
    const int chunksTotal = ntilesLocal * KCH;

    float master[4][2][4];
#pragma unroll
    for (int i = 0; i < 4; i++)
#pragma unroll
        for (int j = 0; j < 2; j++)
#pragma unroll
            for (int e = 0; e < 4; e++) master[i][j][e] = 0.0f;

    // cp.async fill for flat chunk c: tile = bid + (c/8)*NCTA, kc = c%8.
    auto issue = [&](int c, int st) {
        const int tile = bid + (c >> 3) * NCTA;
        const int m0 = (tile >> 5) * BM;
        const int n0 = (tile & 31) * BN;
        const int kh = (c & 7) * BK;
        const uint32_t sb = smem_u32(smem) + (uint32_t)(st * STAGE_U) * 4u;
#pragma unroll
        for (int t = 0; t < 12; t++) {
            const int gid = t * THREADS + tid;
            const uint16_t* srcp;
            uint32_t dst;
            if (gid < 1024) {
                const int row = gid >> 3, cc = gid & 7;
                srcp = g_xh + (size_t)(m0 + row) * NI + kh + cc * 8;
                dst = sb + (uint32_t)(row * USTRIDE + cc * 4) * 4u;
            } else if (gid < 2048) {
                const int j = gid - 1024;
                const int row = j >> 3, cc = j & 7;
                srcp = g_xl + (size_t)(m0 + row) * NI + kh + cc * 8;
                dst = sb + (uint32_t)(APLANE_U + row * USTRIDE + cc * 4) * 4u;
            } else if (gid < 2560) {
                const int j = gid - 2048;
                const int row = j >> 3, cc = j & 7;
                srcp = g_wh + (size_t)(n0 + row) * NI + kh + cc * 8;
                dst = sb + (uint32_t)(2 * APLANE_U + row * USTRIDE + cc * 4) * 4u;
            } else {
                const int j = gid - 2560;
                const int row = j >> 3, cc = j & 7;
                srcp = g_wl + (size_t)(n0 + row) * NI + kh + cc * 8;
                dst = sb + (uint32_t)(2 * APLANE_U + BPLANE_U + row * USTRIDE + cc * 4) * 4u;
            }
            cp_async16(dst, srcp);
        }
        cp_commit();
    };

    issue(0, 0);
    issue(1, 1);

    for (int c = 0; c < chunksTotal; c++) {
        cp_wait<1>();
        __syncthreads();
        const int cur = c & 1;
        const uint32_t* Ah = smem + cur * STAGE_U;
        const uint32_t* Al = Ah + APLANE_U;
        const uint32_t* Bh = Al + APLANE_U;
        const uint32_t* Bl = Bh + BPLANE_U;

        float temp[4][2][4];
#pragma unroll
        for (int s = 0; s < 4; s++) {            // four k16 steps
            const int ko = s * 8;                // u32 offset (16 halves)
            uint32_t bh[2][2], bl[2][2];
#pragma unroll
            for (int nt = 0; nt < 2; nt++) {
                const int col = warpN * 16 + nt * 8 + g;
                const int base = col * USTRIDE + t4 + ko;
                bh[nt][0] = Bh[base];
                bh[nt][1] = Bh[base + 4];
                bl[nt][0] = Bl[base];
                bl[nt][1] = Bl[base + 4];
            }
#pragma unroll
            for (int mp = 0; mp < 2; mp++) {     // mt pairs {0,1} and {2,3}
                uint32_t ah[2][4], al[2][4];
#pragma unroll
                for (int q = 0; q < 2; q++) {
                    const int row = warpM * 64 + (mp * 2 + q) * 16 + g;
                    const int b0 = row * USTRIDE + t4 + ko;
                    const int b8 = (row + 8) * USTRIDE + t4 + ko;
                    ah[q][0] = Ah[b0];     ah[q][1] = Ah[b8];
                    ah[q][2] = Ah[b0 + 4]; ah[q][3] = Ah[b8 + 4];
                    al[q][0] = Al[b0];     al[q][1] = Al[b8];
                    al[q][2] = Al[b0 + 4]; al[q][3] = Al[b8 + 4];
                }
                // per-accumulator order stays hh -> hl -> lh (bit-identical)
#pragma unroll
                for (int q = 0; q < 2; q++)
#pragma unroll
                    for (int nt = 0; nt < 2; nt++) {
                        if ((s & 1) == 0) mma_zero(temp[mp * 2 + q][nt], ah[q], bh[nt]);
                        else              mma_acc(temp[mp * 2 + q][nt], ah[q], bh[nt]);
                    }
#pragma unroll
                for (int q = 0; q < 2; q++)
#pragma unroll
                    for (int nt = 0; nt < 2; nt++)
                        mma_acc(temp[mp * 2 + q][nt], ah[q], bl[nt]);   // h*l
#pragma unroll
                for (int q = 0; q < 2; q++)
#pragma unroll
                    for (int nt = 0; nt < 2; nt++)
                        mma_acc(temp[mp * 2 + q][nt], al[q], bh[nt]);   // l*h
            }
            if (s & 1) {   // flush 6-MMA chain into RN fp32 master
#pragma unroll
                for (int mt = 0; mt < 4; mt++)
#pragma unroll
                    for (int nt = 0; nt < 2; nt++)
#pragma unroll
                        for (int e = 0; e < 4; e++)
                            master[mt][nt][e] += temp[mt][nt][e];
            }
        }

        if ((c & 7) == 7) {
            // tile finished: store cosines, re-zero master
            const int tile = bid + (c >> 3) * NCTA;
            const int m0 = (tile >> 5) * BM;
            const int n0 = (tile & 31) * BN;
#pragma unroll
            for (int mt = 0; mt < 4; mt++) {
                const int r0 = m0 + warpM * 64 + mt * 16 + g;
                const int r1 = r0 + 8;
#pragma unroll
                for (int nt = 0; nt < 2; nt++) {
                    const int cc = n0 + warpN * 16 + nt * 8 + t4 * 2;
                    float2 o0, o1;
                    o0.x = master[mt][nt][0]; o0.y = master[mt][nt][1];
                    o1.x = master[mt][nt][2]; o1.y = master[mt][nt][3];
                    *reinterpret_cast<float2*>(g_cos + (size_t)r0 * NO + cc) = o0;
                    *reinterpret_cast<float2*>(g_cos + (size_t)r1 * NO + cc) = o1;
                }
            }
#pragma unroll
            for (int mt = 0; mt < 4; mt++)
#pragma unroll
                for (int nt = 0; nt < 2; nt++)
#pragma unroll
                    for (int e = 0; e < 4; e++) master[mt][nt][e] = 0.0f;
        }

        __syncthreads();
        if (c + 2 < chunksTotal) issue(c + 2, cur);
        else cp_commit();   // keep wait_group accounting uniform
    }
}

// ---------------------------------------------------------------------------
// Per-row epilogue, 2 rows per block: mean/max/argmax over 2048 cosines,
// nonlinearity, adaptive threshold, WTA. 256 threads; 8 elems/thread/row.
// (exact R7 code — known good)
// ---------------------------------------------------------------------------
__global__ __launch_bounds__(256) void spike_kernel(
    const float* __restrict__ th, float* __restrict__ out) {
    const int r0 = blockIdx.x * 2;
    const int r1 = r0 + 1;
    const int tid = threadIdx.x;
    const int base = tid * 8;
    const float* c0 = g_cos + (size_t)r0 * NO + base;
    const float* c1 = g_cos + (size_t)r1 * NO + base;

    float v0[8], v1[8];
    *reinterpret_cast<float4*>(&v0[0]) = *reinterpret_cast<const float4*>(c0);
    *reinterpret_cast<float4*>(&v0[4]) = *reinterpret_cast<const float4*>(c0 + 4);
    *reinterpret_cast<float4*>(&v1[0]) = *reinterpret_cast<const float4*>(c1);
    *reinterpret_cast<float4*>(&v1[4]) = *reinterpret_cast<const float4*>(c1 + 4);

    float s0 = 0.0f, s1 = 0.0f;
    float mx0 = -3.402823466e+38f, mx1 = -3.402823466e+38f;
    int i0 = 0, i1 = 0;
#pragma unroll
    for (int e = 0; e < 8; e++) {
        s0 += v0[e];
        if (v0[e] > mx0) { mx0 = v0[e]; i0 = base + e; }
        s1 += v1[e];
        if (v1[e] > mx1) { mx1 = v1[e]; i1 = base + e; }
    }
#pragma unroll
    for (int o = 16; o; o >>= 1) {
        s0 += __shfl_xor_sync(0xffffffffu, s0, o);
        s1 += __shfl_xor_sync(0xffffffffu, s1, o);
        float om = __shfl_xor_sync(0xffffffffu, mx0, o);
        int oi = __shfl_xor_sync(0xffffffffu, i0, o);
        if (om > mx0 || (om == mx0 && oi < i0)) { mx0 = om; i0 = oi; }
        om = __shfl_xor_sync(0xffffffffu, mx1, o);
        oi = __shfl_xor_sync(0xffffffffu, i1, o);
        if (om > mx1 || (om == mx1 && oi < i1)) { mx1 = om; i1 = oi; }
    }
    __shared__ float ssum[2][8], smax[2][8];
    __shared__ int sidx[2][8];
    __shared__ float sh_mu[2], sh_q[2];
    __shared__ int sh_arg[2];
    if ((tid & 31) == 0) {
        const int w = tid >> 5;
        ssum[0][w] = s0; smax[0][w] = mx0; sidx[0][w] = i0;
        ssum[1][w] = s1; smax[1][w] = mx1; sidx[1][w] = i1;
    }
    __syncthreads();
    if (tid == 0 || tid == 32) {          // warp0 finalizes row0, warp1 row1
        const int r = tid >> 5;
        float ts = 0.0f, tm = -3.402823466e+38f;
        int ti = 0;
#pragma unroll
        for (int w = 0; w < 8; w++) {
            ts += ssum[r][w];
            if (smax[r][w] > tm || (smax[r][w] == tm && sidx[r][w] < ti)) {
                tm = smax[r][w]; ti = sidx[r][w];
            }
        }
        const float mu = ts * (1.0f / NO);
        const float c = tm - mu;
        const float a = fabsf(c);
        const float vmax = copysignf((a + 10.0f * a * a * a) * 50.0f, c);
        sh_mu[r] = mu;
        sh_q[r] = vmax * 0.25f;
        sh_arg[r] = ti;
    }
    __syncthreads();

    float t[8];
    *reinterpret_cast<float4*>(&t[0]) = *reinterpret_cast<const float4*>(th + base);
    *reinterpret_cast<float4*>(&t[4]) = *reinterpret_cast<const float4*>(th + base + 4);

    const float mu0 = sh_mu[0], q0 = sh_q[0];
    const float mu1 = sh_mu[1], q1 = sh_q[1];
    float sp0[8], sp1[8];
    int any0 = 0, any1 = 0;
#pragma unroll
    for (int e = 0; e < 8; e++) {
        float c = v0[e] - mu0;
        float a = fabsf(c);
        float vm = copysignf((a + 10.0f * a * a * a) * 50.0f, c);
        float eff = fmaxf(fminf(t[e], q0), 0.01f);
        sp0[e] = (vm >= eff) ? 1.0f : 0.0f;
        any0 |= (vm >= eff);
        c = v1[e] - mu1;
        a = fabsf(c);
        vm = copysignf((a + 10.0f * a * a * a) * 50.0f, c);
        eff = fmaxf(fminf(t[e], q1), 0.01f);
        sp1[e] = (vm >= eff) ? 1.0f : 0.0f;
        any1 |= (vm >= eff);
    }
    const int ab0 = __syncthreads_or(any0);
    const int ab1 = __syncthreads_or(any1);
    if (!ab0) {
        const int argi = sh_arg[0];
#pragma unroll
        for (int e = 0; e < 8; e++) sp0[e] = (base + e == argi) ? 1.0f : 0.0f;
    }
    if (!ab1) {
        const int argi = sh_arg[1];
#pragma unroll
        for (int e = 0; e < 8; e++) sp1[e] = (base + e == argi) ? 1.0f : 0.0f;
    }
    float* d0 = out + (size_t)r0 * NO + base;
    float* d1 = out + (size_t)r1 * NO + base;
    *reinterpret_cast<float4*>(d0) = *reinterpret_cast<float4*>(&sp0[0]);
    *reinterpret_cast<float4*>(d0 + 4) = *reinterpret_cast<float4*>(&sp0[4]);
    *reinterpret_cast<float4*>(d1) = *reinterpret_cast<float4*>(&sp1[0]);
    *reinterpret_cast<float4*>(d1 + 4) = *reinterpret_cast<float4*>(&sp1[4]);
}

// ---------------------------------------------------------------------------
extern "C" void kernel_launch(void* const* d_in, const int* in_sizes, int n_in,
                              void* d_out, int out_size) {
    const float* X = (const float*)d_in[0];   // [16384, 512]
    const float* W = (const float*)d_in[1];   // [2048, 512]
    const float* TH = (const float*)d_in[2];  // [2048]
    float* OUT = (float*)d_out;               // [16384, 2048]

    uint16_t *xh, *xl, *wh, *wl;
    cudaGetSymbolAddress((void**)&xh, g_xh);
    cudaGetSymbolAddress((void**)&xl, g_xl);
    cudaGetSymbolAddress((void**)&wh, g_wh);
    cudaGetSymbolAddress((void**)&wl, g_wl);

    cudaFuncSetAttribute(gemm_tc, cudaFuncAttributeMaxDynamicSharedMemorySize, SMEM_BYTES);

    prep_kernel<<<NB, 128>>>(X, xh, xl);
    prep_kernel<<<NO, 128>>>(W, wh, wl);
    gemm_tc<<<NCTA, THREADS, SMEM_BYTES>>>();
    spike_kernel<<<NB / 2, 256>>>(TH, OUT);
}

// round 17
// speedup vs baseline: 1.1250x; 1.1250x over previous
#include <cuda_runtime.h>
#include <cstdint>

#define NB 16384
#define NI 512
#define NO 2048

#define BM 128
#define BN 64
#define BK 64
#define KCH (NI / BK)     // 8
#define THREADS 128
#define USTRIDE 36                          // u32 per row: 32 data + 4 pad
#define APLANE_U (128 * USTRIDE)            // 4608
#define BPLANE_U (64 * USTRIDE)             // 2304
#define STAGE_U (2 * APLANE_U + 2 * BPLANE_U)  // 13824 u32 = 55296 B
#define SMEM_BYTES (2 * STAGE_U * 4)        // 110592 B

// ---------------------------------------------------------------------------
// scratch (device globals — no allocations allowed)
// ---------------------------------------------------------------------------
__device__ uint16_t g_xh[(size_t)NB * NI];   // fp16 hi plane of x/||x||
__device__ uint16_t g_xl[(size_t)NB * NI];   // fp16 lo plane
__device__ uint16_t g_wh[(size_t)NO * NI];
__device__ uint16_t g_wl[(size_t)NO * NI];
__device__ float g_cos[(size_t)NB * NO];

// ---------------------------------------------------------------------------
// helpers
// ---------------------------------------------------------------------------
__device__ __forceinline__ void cp_async16(uint32_t dst, const void* src) {
    asm volatile("cp.async.cg.shared.global [%0], [%1], 16;" :: "r"(dst), "l"(src));
}
__device__ __forceinline__ uint32_t smem_u32(const void* p) {
    uint32_t a;
    asm("{ .reg .u64 t; cvta.to.shared.u64 t, %1; cvt.u32.u64 %0, t; }" : "=r"(a) : "l"(p));
    return a;
}
__device__ __forceinline__ void cp_commit() {
    asm volatile("cp.async.commit_group;" ::: "memory");
}
template <int N>
__device__ __forceinline__ void cp_wait() {
    asm volatile("cp.async.wait_group %0;" :: "n"(N) : "memory");
}
// fp16 2-split: x = h + l (exact to ~2^-24 relative)
__device__ __forceinline__ void f16_split(float x, uint16_t& h, uint16_t& l) {
    asm("cvt.rn.f16.f32 %0, %1;" : "=h"(h) : "f"(x));
    float hf;
    asm("cvt.f32.f16 %0, %1;" : "=f"(hf) : "h"(h));
    const float r = x - hf;
    asm("cvt.rn.f16.f32 %0, %1;" : "=h"(l) : "f"(r));
}
// d += a*b   (m16n8k16 fp16 -> fp32)
__device__ __forceinline__ void mma_acc(float* d, const uint32_t* a, const uint32_t* b) {
    asm volatile(
        "mma.sync.aligned.m16n8k16.row.col.f32.f16.f16.f32 "
        "{%0,%1,%2,%3}, {%4,%5,%6,%7}, {%8,%9}, {%0,%1,%2,%3};"
        : "+f"(d[0]), "+f"(d[1]), "+f"(d[2]), "+f"(d[3])
        : "r"(a[0]), "r"(a[1]), "r"(a[2]), "r"(a[3]), "r"(b[0]), "r"(b[1]));
}
// d = a*b (fresh accumulation chain)
__device__ __forceinline__ void mma_zero(float* d, const uint32_t* a, const uint32_t* b) {
    asm volatile(
        "mma.sync.aligned.m16n8k16.row.col.f32.f16.f16.f32 "
        "{%0,%1,%2,%3}, {%4,%5,%6,%7}, {%8,%9}, {%10,%11,%12,%13};"
        : "=f"(d[0]), "=f"(d[1]), "=f"(d[2]), "=f"(d[3])
        : "r"(a[0]), "r"(a[1]), "r"(a[2]), "r"(a[3]), "r"(b[0]), "r"(b[1]),
          "f"(0.0f), "f"(0.0f), "f"(0.0f), "f"(0.0f));
}

// ---------------------------------------------------------------------------
// prep: normalize each row (/(max(||row||, eps))) and write fp16 hi/lo planes.
// ---------------------------------------------------------------------------
__global__ __launch_bounds__(128) void prep_kernel(
    const float* __restrict__ src, uint16_t* __restrict__ Hi,
    uint16_t* __restrict__ Lo) {
    const int row = blockIdx.x;
    const int tid = threadIdx.x;
    const float4 v = reinterpret_cast<const float4*>(src + (size_t)row * NI)[tid];
    float s = v.x * v.x + v.y * v.y + v.z * v.z + v.w * v.w;
#pragma unroll
    for (int o = 16; o; o >>= 1) s += __shfl_xor_sync(0xffffffffu, s, o);
    __shared__ float ws[4];
    __shared__ float sh_inv;
    if ((tid & 31) == 0) ws[tid >> 5] = s;
    __syncthreads();
    if (tid == 0) {
        const float t = ws[0] + ws[1] + ws[2] + ws[3];
        sh_inv = 1.0f / fmaxf(sqrtf(t), 1e-8f);
    }
    __syncthreads();
    const float inv = sh_inv;

    uint16_t h0, l0, h1, l1, h2, l2, h3, l3;
    f16_split(v.x * inv, h0, l0);
    f16_split(v.y * inv, h1, l1);
    f16_split(v.z * inv, h2, l2);
    f16_split(v.w * inv, h3, l3);
    uint2 ph, pl;
    ph.x = (uint32_t)h0 | ((uint32_t)h1 << 16);
    ph.y = (uint32_t)h2 | ((uint32_t)h3 << 16);
    pl.x = (uint32_t)l0 | ((uint32_t)l1 << 16);
    pl.y = (uint32_t)l2 | ((uint32_t)l3 << 16);
    reinterpret_cast<uint2*>(Hi + (size_t)row * NI)[tid] = ph;
    reinterpret_cast<uint2*>(Lo + (size_t)row * NI)[tid] = pl;
}

// ---------------------------------------------------------------------------
// 3xFP16 warp-mma GEMM on pre-normalized pre-split planes:
//   cos[b,o] = dot(xn[b,:], wn[o,:])  via hh + hl + lh
// CTA 128x64x64, 2-stage cp.async smem, 4 warps (2m x 2n), warp 64x32
// (halves redundant A fragment traffic through the smem crossbar vs 8-warp
// layout). 6-MMA temp chains (zeroed at k16-steps 0/2, RN-flushed after 1/3)
// -- per-output arithmetic stream identical to R7 (bit-identical results).
// ---------------------------------------------------------------------------
__global__ __launch_bounds__(THREADS, 2)
void gemm_tc() {
    extern __shared__ uint32_t smem[];   // [2 stages][Ah|Al|Bh|Bl]

    const int tid = threadIdx.x;
    const int wid = tid >> 5;
    const int lane = tid & 31;
    const int m0 = blockIdx.y * BM;
    const int n0 = blockIdx.x * BN;
    const int warpM = wid & 1;   // 2
    const int warpN = wid >> 1;  // 2
    const int g = lane >> 2;     // 0..7
    const int t4 = lane & 3;     // 0..3

    float master[4][4][4];
#pragma unroll
    for (int i = 0; i < 4; i++)
#pragma unroll
        for (int j = 0; j < 4; j++)
#pragma unroll
            for (int e = 0; e < 4; e++) master[i][j][e] = 0.0f;

    // cp.async fill: 3072 16-B chunks per stage, 24 per thread.
    auto issue = [&](int kc, int st) {
        const int kh = kc * BK;
        const uint32_t sb = smem_u32(smem) + (uint32_t)(st * STAGE_U) * 4u;
#pragma unroll
        for (int t = 0; t < 24; t++) {
            const int gid = t * THREADS + tid;
            const uint16_t* srcp;
            uint32_t dst;
            if (gid < 1024) {
                const int row = gid >> 3, c = gid & 7;
                srcp = g_xh + (size_t)(m0 + row) * NI + kh + c * 8;
                dst = sb + (uint32_t)(row * USTRIDE + c * 4) * 4u;
            } else if (gid < 2048) {
                const int j = gid - 1024;
                const int row = j >> 3, c = j & 7;
                srcp = g_xl + (size_t)(m0 + row) * NI + kh + c * 8;
                dst = sb + (uint32_t)(APLANE_U + row * USTRIDE + c * 4) * 4u;
            } else if (gid < 2560) {
                const int j = gid - 2048;
                const int row = j >> 3, c = j & 7;
                srcp = g_wh + (size_t)(n0 + row) * NI + kh + c * 8;
                dst = sb + (uint32_t)(2 * APLANE_U + row * USTRIDE + c * 4) * 4u;
            } else {
                const int j = gid - 2560;
                const int row = j >> 3, c = j & 7;
                srcp = g_wl + (size_t)(n0 + row) * NI + kh + c * 8;
                dst = sb + (uint32_t)(2 * APLANE_U + BPLANE_U + row * USTRIDE + c * 4) * 4u;
            }
            cp_async16(dst, srcp);
        }
        cp_commit();
    };

    issue(0, 0);
    issue(1, 1);

    for (int kc = 0; kc < KCH; kc++) {
        cp_wait<1>();
        __syncthreads();
        const int cur = kc & 1;
        const uint32_t* Ah = smem + cur * STAGE_U;
        const uint32_t* Al = Ah + APLANE_U;
        const uint32_t* Bh = Al + APLANE_U;
        const uint32_t* Bl = Bh + BPLANE_U;

        float temp[4][4][4];
#pragma unroll
        for (int s = 0; s < 4; s++) {            // four k16 steps
            const int ko = s * 8;                // u32 offset (16 halves)
            uint32_t bh[4][2], bl[4][2];
#pragma unroll
            for (int nt = 0; nt < 4; nt++) {
                const int col = warpN * 32 + nt * 8 + g;
                const int base = col * USTRIDE + t4 + ko;
                bh[nt][0] = Bh[base];
                bh[nt][1] = Bh[base + 4];
                bl[nt][0] = Bl[base];
                bl[nt][1] = Bl[base + 4];
            }
#pragma unroll
            for (int mp = 0; mp < 2; mp++) {     // mt pairs {0,1} and {2,3}
                uint32_t ah[2][4], al[2][4];
#pragma unroll
                for (int q = 0; q < 2; q++) {
                    const int row = warpM * 64 + (mp * 2 + q) * 16 + g;
                    const int b0 = row * USTRIDE + t4 + ko;
                    const int b8 = (row + 8) * USTRIDE + t4 + ko;
                    ah[q][0] = Ah[b0];     ah[q][1] = Ah[b8];
                    ah[q][2] = Ah[b0 + 4]; ah[q][3] = Ah[b8 + 4];
                    al[q][0] = Al[b0];     al[q][1] = Al[b8];
                    al[q][2] = Al[b0 + 4]; al[q][3] = Al[b8 + 4];
                }
                // per-accumulator order stays hh -> hl -> lh (bit-identical)
#pragma unroll
                for (int q = 0; q < 2; q++)
#pragma unroll
                    for (int nt = 0; nt < 4; nt++) {
                        if ((s & 1) == 0) mma_zero(temp[mp * 2 + q][nt], ah[q], bh[nt]);
                        else              mma_acc(temp[mp * 2 + q][nt], ah[q], bh[nt]);
                    }
#pragma unroll
                for (int q = 0; q < 2; q++)
#pragma unroll
                    for (int nt = 0; nt < 4; nt++)
                        mma_acc(temp[mp * 2 + q][nt], ah[q], bl[nt]);   // h*l
#pragma unroll
                for (int q = 0; q < 2; q++)
#pragma unroll
                    for (int nt = 0; nt < 4; nt++)
                        mma_acc(temp[mp * 2 + q][nt], al[q], bh[nt]);   // l*h
            }
            if (s & 1) {   // flush 6-MMA chain into RN fp32 master
#pragma unroll
                for (int mt = 0; mt < 4; mt++)
#pragma unroll
                    for (int nt = 0; nt < 4; nt++)
#pragma unroll
                        for (int e = 0; e < 4; e++)
                            master[mt][nt][e] += temp[mt][nt][e];
            }
        }
        __syncthreads();
        if (kc + 2 < KCH) issue(kc + 2, cur);
        else cp_commit();   // keep wait_group accounting uniform
    }

    // epilogue: planes are pre-normalized, so master IS the cosine
#pragma unroll
    for (int mt = 0; mt < 4; mt++) {
        const int r0 = m0 + warpM * 64 + mt * 16 + g;
        const int r1 = r0 + 8;
#pragma unroll
        for (int nt = 0; nt < 4; nt++) {
            const int c = n0 + warpN * 32 + nt * 8 + t4 * 2;
            float2 o0, o1;
            o0.x = master[mt][nt][0]; o0.y = master[mt][nt][1];
            o1.x = master[mt][nt][2]; o1.y = master[mt][nt][3];
            *reinterpret_cast<float2*>(g_cos + (size_t)r0 * NO + c) = o0;
            *reinterpret_cast<float2*>(g_cos + (size_t)r1 * NO + c) = o1;
        }
    }
}

// ---------------------------------------------------------------------------
// Per-row epilogue, 2 rows per block: mean/max/argmax over 2048 cosines,
// nonlinearity, adaptive threshold, WTA. 256 threads; 8 elems/thread/row.
// (exact R7 code — known good)
// ---------------------------------------------------------------------------
__global__ __launch_bounds__(256) void spike_kernel(
    const float* __restrict__ th, float* __restrict__ out) {
    const int r0 = blockIdx.x * 2;
    const int r1 = r0 + 1;
    const int tid = threadIdx.x;
    const int base = tid * 8;
    const float* c0 = g_cos + (size_t)r0 * NO + base;
    const float* c1 = g_cos + (size_t)r1 * NO + base;

    float v0[8], v1[8];
    *reinterpret_cast<float4*>(&v0[0]) = *reinterpret_cast<const float4*>(c0);
    *reinterpret_cast<float4*>(&v0[4]) = *reinterpret_cast<const float4*>(c0 + 4);
    *reinterpret_cast<float4*>(&v1[0]) = *reinterpret_cast<const float4*>(c1);
    *reinterpret_cast<float4*>(&v1[4]) = *reinterpret_cast<const float4*>(c1 + 4);

    float s0 = 0.0f, s1 = 0.0f;
    float mx0 = -3.402823466e+38f, mx1 = -3.402823466e+38f;
    int i0 = 0, i1 = 0;
#pragma unroll
    for (int e = 0; e < 8; e++) {
        s0 += v0[e];
        if (v0[e] > mx0) { mx0 = v0[e]; i0 = base + e; }
        s1 += v1[e];
        if (v1[e] > mx1) { mx1 = v1[e]; i1 = base + e; }
    }
#pragma unroll
    for (int o = 16; o; o >>= 1) {
        s0 += __shfl_xor_sync(0xffffffffu, s0, o);
        s1 += __shfl_xor_sync(0xffffffffu, s1, o);
        float om = __shfl_xor_sync(0xffffffffu, mx0, o);
        int oi = __shfl_xor_sync(0xffffffffu, i0, o);
        if (om > mx0 || (om == mx0 && oi < i0)) { mx0 = om; i0 = oi; }
        om = __shfl_xor_sync(0xffffffffu, mx1, o);
        oi = __shfl_xor_sync(0xffffffffu, i1, o);
        if (om > mx1 || (om == mx1 && oi < i1)) { mx1 = om; i1 = oi; }
    }
    __shared__ float ssum[2][8], smax[2][8];
    __shared__ int sidx[2][8];
    __shared__ float sh_mu[2], sh_q[2];
    __shared__ int sh_arg[2];
    if ((tid & 31) == 0) {
        const int w = tid >> 5;
        ssum[0][w] = s0; smax[0][w] = mx0; sidx[0][w] = i0;
        ssum[1][w] = s1; smax[1][w] = mx1; sidx[1][w] = i1;
    }
    __syncthreads();
    if (tid == 0 || tid == 32) {          // warp0 finalizes row0, warp1 row1
        const int r = tid >> 5;
        float ts = 0.0f, tm = -3.402823466e+38f;
        int ti = 0;
#pragma unroll
        for (int w = 0; w < 8; w++) {
            ts += ssum[r][w];
            if (smax[r][w] > tm || (smax[r][w] == tm && sidx[r][w] < ti)) {
                tm = smax[r][w]; ti = sidx[r][w];
            }
        }
        const float mu = ts * (1.0f / NO);
        const float c = tm - mu;
        const float a = fabsf(c);
        const float vmax = copysignf((a + 10.0f * a * a * a) * 50.0f, c);
        sh_mu[r] = mu;
        sh_q[r] = vmax * 0.25f;
        sh_arg[r] = ti;
    }
    __syncthreads();

    float t[8];
    *reinterpret_cast<float4*>(&t[0]) = *reinterpret_cast<const float4*>(th + base);
    *reinterpret_cast<float4*>(&t[4]) = *reinterpret_cast<const float4*>(th + base + 4);

    const float mu0 = sh_mu[0], q0 = sh_q[0];
    const float mu1 = sh_mu[1], q1 = sh_q[1];
    float sp0[8], sp1[8];
    int any0 = 0, any1 = 0;
#pragma unroll
    for (int e = 0; e < 8; e++) {
        float c = v0[e] - mu0;
        float a = fabsf(c);
        float vm = copysignf((a + 10.0f * a * a * a) * 50.0f, c);
        float eff = fmaxf(fminf(t[e], q0), 0.01f);
        sp0[e] = (vm >= eff) ? 1.0f : 0.0f;
        any0 |= (vm >= eff);
        c = v1[e] - mu1;
        a = fabsf(c);
        vm = copysignf((a + 10.0f * a * a * a) * 50.0f, c);
        eff = fmaxf(fminf(t[e], q1), 0.01f);
        sp1[e] = (vm >= eff) ? 1.0f : 0.0f;
        any1 |= (vm >= eff);
    }
    const int ab0 = __syncthreads_or(any0);
    const int ab1 = __syncthreads_or(any1);
    if (!ab0) {
        const int argi = sh_arg[0];
#pragma unroll
        for (int e = 0; e < 8; e++) sp0[e] = (base + e == argi) ? 1.0f : 0.0f;
    }
    if (!ab1) {
        const int argi = sh_arg[1];
#pragma unroll
        for (int e = 0; e < 8; e++) sp1[e] = (base + e == argi) ? 1.0f : 0.0f;
    }
    float* d0 = out + (size_t)r0 * NO + base;
    float* d1 = out + (size_t)r1 * NO + base;
    *reinterpret_cast<float4*>(d0) = *reinterpret_cast<float4*>(&sp0[0]);
    *reinterpret_cast<float4*>(d0 + 4) = *reinterpret_cast<float4*>(&sp0[4]);
    *reinterpret_cast<float4*>(d1) = *reinterpret_cast<float4*>(&sp1[0]);
    *reinterpret_cast<float4*>(d1 + 4) = *reinterpret_cast<float4*>(&sp1[4]);
}

// ---------------------------------------------------------------------------
extern "C" void kernel_launch(void* const* d_in, const int* in_sizes, int n_in,
                              void* d_out, int out_size) {
    const float* X = (const float*)d_in[0];   // [16384, 512]
    const float* W = (const float*)d_in[1];   // [2048, 512]
    const float* TH = (const float*)d_in[2];  // [2048]
    float* OUT = (float*)d_out;               // [16384, 2048]

    uint16_t *xh, *xl, *wh, *wl;
    cudaGetSymbolAddress((void**)&xh, g_xh);
    cudaGetSymbolAddress((void**)&xl, g_xl);
    cudaGetSymbolAddress((void**)&wh, g_wh);
    cudaGetSymbolAddress((void**)&wl, g_wl);

    cudaFuncSetAttribute(gemm_tc, cudaFuncAttributeMaxDynamicSharedMemorySize, SMEM_BYTES);

    prep_kernel<<<NB, 128>>>(X, xh, xl);
    prep_kernel<<<NO, 128>>>(W, wh, wl);
    gemm_tc<<<dim3(NO / BN, NB / BM), THREADS, SMEM_BYTES>>>();
    spike_kernel<<<NB / 2, 256>>>(TH, OUT);
}